// round 14
// baseline (speedup 1.0000x reference)
#include <cuda_runtime.h>

// Ping-pong scratch (device globals — no allocation allowed).
__device__ float g_buf1[4 * 3 * 96  * 128];   // stage1 out
__device__ float g_buf2[4 * 3 * 192 * 256];   // stage2 out
__device__ float g_buf3[4 * 3 * 384 * 512];   // stage3 out

__device__ __forceinline__ void pdl_trigger() {
    asm volatile("griddepcontrol.launch_dependents;" ::: "memory");
}
__device__ __forceinline__ void pdl_wait() {
    asm volatile("griddepcontrol.wait;" ::: "memory");
}
__device__ __forceinline__ void prefetch_l2(const void* p) {
    asm volatile("prefetch.global.L2 [%0];" :: "l"(p));
}

// One convex-upsample stage (scale=2). Thread = one SOURCE pixel (n,h,w),
// producing the 2x2 output quad for all 3 channels.
// mask layout [N,36,H,W], channel c = k*4 + i*2 + j.
// Softmax over k without max-subtraction (exp of ~N(0,1) safe; identical).
//
// MODE 0: first stage — single pass, no wait.
// MODE 1: L2-resident mask (fits 126MB L2): phase-1 computes softmax
//         denominators from mask (producer-independent) BEFORE pdl_wait,
//         overlapping this stage's mask DRAM stream with the producer;
//         phase-2 re-reads mask from L2 (hit) and accumulates.
// MODE 2: streaming mask (too big for L2): register-free prefetch.global.L2
//         sweep over this thread's 36 mask lines before pdl_wait, then the
//         proven single-pass loop.
template<int H, int WSHIFT, bool FIRST, int TPB, int MINB, int MODE, bool TRIG>
__global__ __launch_bounds__(TPB, MINB)
void convex_up(const float* __restrict__ in_flow,
               const float* __restrict__ in_dz,
               const float* __restrict__ mask,
               float* __restrict__ out)
{
    constexpr int W  = 1 << WSHIFT;
    constexpr int HW = H * W;

    if (TRIG) pdl_trigger();   // release dependent stage's CTAs immediately

    const int idx = blockIdx.x * TPB + threadIdx.x;   // grid exact: no guard
    const int n = blockIdx.y;
    const int w = idx & (W - 1);
    const int h = idx >> WSHIFT;

    const float* mb = mask + (size_t)n * (36 * HW) + idx;   // + c*HW per channel
    const float* pf = in_flow + (size_t)n * (FIRST ? 2 * HW : 3 * HW);
    const float* pd = in_dz   + (size_t)n * (FIRST ?     HW : 3 * HW);

    // Hoisted edge predicates (producer-independent).
    const bool okl = (w > 0), okr = (w + 1 < W);
    const bool oku = (h > 0), okd = (h + 1 < H);

    float sum[4] = {0.f, 0.f, 0.f, 0.f};
    float inv[4];

    if (MODE == 1) {
        // ---- phase 1: mask fetch + softmax denominators, pre-wait ----
#pragma unroll
        for (int k = 0; k < 9; k++)
#pragma unroll
            for (int q = 0; q < 4; q++)
                sum[q] += __expf(__ldcg(mb + (size_t)(k * 4 + q) * HW));
#pragma unroll
        for (int q = 0; q < 4; q++) inv[q] = __fdividef(1.0f, sum[q]);
        pdl_wait();
    } else if (MODE == 2) {
        // ---- register-free L2 warm-up of this thread's mask lines ----
#pragma unroll
        for (int c = 0; c < 36; c++)
            prefetch_l2(mb + (size_t)c * HW);
        pdl_wait();
    }

    float acc[4][3];
#pragma unroll
    for (int q = 0; q < 4; q++) acc[q][0] = acc[q][1] = acc[q][2] = 0.f;

#pragma unroll
    for (int k = 0; k < 9; k++) {
        const int dy = k / 3 - 1;
        const int dx = k % 3 - 1;
        const bool ok = (dy == 0 || (dy < 0 ? oku : okd)) &&
                        (dx == 0 || (dx < 0 ? okl : okr));
        float v0 = 0.f, v1 = 0.f, v2 = 0.f;
        if (ok) {
            const int off = ((h + dy) << WSHIFT) + (w + dx);
            v0 = pf[off];
            v1 = pf[off + HW];
            v2 = pd[off];
        }
#pragma unroll
        for (int q = 0; q < 4; q++) {
            float e;
            if (MODE == 1)
                e = __expf(__ldcg(mb + (size_t)(k * 4 + q) * HW));  // L2 hit
            else
                e = __expf(__ldcs(mb + (size_t)(k * 4 + q) * HW));
            if (MODE != 1) sum[q] += e;
            acc[q][0] = fmaf(e, v0, acc[q][0]);
            acc[q][1] = fmaf(e, v1, acc[q][1]);
            acc[q][2] = fmaf(e, v2, acc[q][2]);
        }
    }

    if (MODE != 1) {
#pragma unroll
        for (int q = 0; q < 4; q++) inv[q] = __fdividef(1.0f, sum[q]);
    }

    // out [N,3,2H,2W]; quad q = i*2+j -> pixel (2h+i, 2w+j). float2 stores.
    constexpr int W2 = W << 1;
    constexpr size_t HW4 = (size_t)HW * 4;
    float* ob = out + (size_t)n * (3 * HW4)
                    + ((size_t)h << (WSHIFT + 2)) + (w << 1);
#pragma unroll
    for (int ch = 0; ch < 3; ch++) {
        const float pm = (ch < 2) ? 2.0f : 1.0f;   // flow premul per stage
#pragma unroll
        for (int i = 0; i < 2; i++) {
            float2 v;
            v.x = pm * acc[i * 2 + 0][ch] * inv[i * 2 + 0];
            v.y = pm * acc[i * 2 + 1][ch] * inv[i * 2 + 1];
            *reinterpret_cast<float2*>(ob + (size_t)ch * HW4 + (size_t)i * W2) = v;
        }
    }
}

template<int H, int WSHIFT, bool FIRST, int TPB, int MINB, int MODE, bool TRIG>
static inline void launch_stage(const float* pf, const float* pd,
                                const float* mask, float* out, int N)
{
    constexpr int HW = H << WSHIFT;
    static_assert(HW % TPB == 0, "exact grid");

    cudaLaunchConfig_t cfg = {};
    cfg.gridDim  = dim3(HW / TPB, N);
    cfg.blockDim = dim3(TPB);
    cudaLaunchAttribute attr[1];
    attr[0].id = cudaLaunchAttributeProgrammaticStreamSerialization;
    attr[0].val.programmaticStreamSerializationAllowed = 1;
    if (MODE != 0) { cfg.attrs = attr; cfg.numAttrs = 1; }

    cudaLaunchKernelEx(&cfg,
                       convex_up<H, WSHIFT, FIRST, TPB, MINB, MODE, TRIG>,
                       pf, pd, mask, out);
}

extern "C" void kernel_launch(void* const* d_in, const int* in_sizes, int n_in,
                              void* d_out, int out_size)
{
    const float* flow16 = (const float*)d_in[0];  // [4,2,48,64]
    const float* dz16   = (const float*)d_in[1];  // [4,1,48,64]
    const float* mask16 = (const float*)d_in[2];  // [4,36,48,64]
    const float* mask8  = (const float*)d_in[3];  // [4,36,96,128]
    const float* mask4  = (const float*)d_in[4];  // [4,36,192,256]
    const float* mask2  = (const float*)d_in[5];  // [4,36,384,512]
    float* out = (float*)d_out;                   // [4,3,768,1024]

    float *buf1, *buf2, *buf3;
    cudaGetSymbolAddress((void**)&buf1, g_buf1);
    cudaGetSymbolAddress((void**)&buf2, g_buf2);
    cudaGetSymbolAddress((void**)&buf3, g_buf3);

    const int N = 4;

    // Stage 1: no wait, trigger.
    launch_stage<48, 6, true, 64, 8, 0, true>(flow16, dz16, mask16, buf1, N);
    // Stage 2: phase-1 denominators (mask8 = 9.4MB, L2-resident), trigger.
    launch_stage<96, 7, false, 64, 8, 1, true>(buf1, buf1 + 2 * 96 * 128,
                                               mask8, buf2, N);
    // Stage 3: phase-1 denominators (mask4 = 37.6MB, L2-resident), trigger.
    launch_stage<192, 8, false, 256, 5, 1, true>(buf2, buf2 + 2 * 192 * 256,
                                                 mask4, buf3, N);
    // Stage 4: mask2 = 113MB streams; prefetch warm-up + single pass, no trigger.
    launch_stage<384, 9, false, 256, 5, 2, false>(buf3, buf3 + 2 * 384 * 512,
                                                  mask2, out, N);
}

// round 15
// speedup vs baseline: 1.0913x; 1.0913x over previous
#include <cuda_runtime.h>

// Ping-pong scratch (device globals — no allocation allowed).
__device__ float g_buf1[4 * 3 * 96  * 128];   // stage1 out
__device__ float g_buf2[4 * 3 * 192 * 256];   // stage2 out
__device__ float g_buf3[4 * 3 * 384 * 512];   // stage3 out

__device__ __forceinline__ void pdl_trigger() {
    asm volatile("griddepcontrol.launch_dependents;" ::: "memory");
}
__device__ __forceinline__ void pdl_wait() {
    asm volatile("griddepcontrol.wait;" ::: "memory");
}

// One convex-upsample stage (scale=2). Thread = one SOURCE pixel (n,h,w),
// producing the 2x2 output quad for all 3 channels.
// mask layout [N,36,H,W], channel c = k*4 + i*2 + j.
// Softmax over k without max-subtraction (exp of ~N(0,1) safe; identical).
//
// MODE 0: first stage — single pass, no wait.
// MODE 1: L2-resident mask (mask8 9.4MB / mask4 37.6MB << 126MB L2):
//         phase-1 computes softmax denominators BEFORE pdl_wait (overlaps
//         this stage's mask DRAM stream with the producer's execution);
//         phase-2 re-reads mask from L2 and accumulates.   [R14: -1.3us]
// MODE 3: streaming mask (mask2 113MB): plain pdl_wait then the proven
//         single-pass loop. (R14's prefetch sweep regressed; reverted.)
template<int H, int WSHIFT, bool FIRST, int TPB, int MINB, int MODE, bool TRIG>
__global__ __launch_bounds__(TPB, MINB)
void convex_up(const float* __restrict__ in_flow,
               const float* __restrict__ in_dz,
               const float* __restrict__ mask,
               float* __restrict__ out)
{
    constexpr int W  = 1 << WSHIFT;
    constexpr int HW = H * W;

    if (TRIG) pdl_trigger();   // release dependent stage's CTAs immediately

    const int idx = blockIdx.x * TPB + threadIdx.x;   // grid exact: no guard
    const int n = blockIdx.y;
    const int w = idx & (W - 1);
    const int h = idx >> WSHIFT;

    const float* mb = mask + (size_t)n * (36 * HW) + idx;   // + c*HW per channel
    const float* pf = in_flow + (size_t)n * (FIRST ? 2 * HW : 3 * HW);
    const float* pd = in_dz   + (size_t)n * (FIRST ?     HW : 3 * HW);

    // Hoisted edge predicates (producer-independent).
    const bool okl = (w > 0), okr = (w + 1 < W);
    const bool oku = (h > 0), okd = (h + 1 < H);

    float sum[4] = {0.f, 0.f, 0.f, 0.f};
    float inv[4];

    if (MODE == 1) {
        // ---- phase 1: mask fetch + softmax denominators, pre-wait ----
#pragma unroll
        for (int k = 0; k < 9; k++)
#pragma unroll
            for (int q = 0; q < 4; q++)
                sum[q] += __expf(__ldcg(mb + (size_t)(k * 4 + q) * HW));
#pragma unroll
        for (int q = 0; q < 4; q++) inv[q] = __fdividef(1.0f, sum[q]);
        pdl_wait();
    } else if (MODE == 3) {
        pdl_wait();
    }

    float acc[4][3];
#pragma unroll
    for (int q = 0; q < 4; q++) acc[q][0] = acc[q][1] = acc[q][2] = 0.f;

#pragma unroll
    for (int k = 0; k < 9; k++) {
        const int dy = k / 3 - 1;
        const int dx = k % 3 - 1;
        const bool ok = (dy == 0 || (dy < 0 ? oku : okd)) &&
                        (dx == 0 || (dx < 0 ? okl : okr));
        float v0 = 0.f, v1 = 0.f, v2 = 0.f;
        if (ok) {
            const int off = ((h + dy) << WSHIFT) + (w + dx);
            v0 = pf[off];
            v1 = pf[off + HW];
            v2 = pd[off];
        }
#pragma unroll
        for (int q = 0; q < 4; q++) {
            float e;
            if (MODE == 1)
                e = __expf(__ldcg(mb + (size_t)(k * 4 + q) * HW));  // L2 hit
            else
                e = __expf(__ldcs(mb + (size_t)(k * 4 + q) * HW));
            if (MODE != 1) sum[q] += e;
            acc[q][0] = fmaf(e, v0, acc[q][0]);
            acc[q][1] = fmaf(e, v1, acc[q][1]);
            acc[q][2] = fmaf(e, v2, acc[q][2]);
        }
    }

    if (MODE != 1) {
#pragma unroll
        for (int q = 0; q < 4; q++) inv[q] = __fdividef(1.0f, sum[q]);
    }

    // out [N,3,2H,2W]; quad q = i*2+j -> pixel (2h+i, 2w+j). float2 stores.
    constexpr int W2 = W << 1;
    constexpr size_t HW4 = (size_t)HW * 4;
    float* ob = out + (size_t)n * (3 * HW4)
                    + ((size_t)h << (WSHIFT + 2)) + (w << 1);
#pragma unroll
    for (int ch = 0; ch < 3; ch++) {
        const float pm = (ch < 2) ? 2.0f : 1.0f;   // flow premul per stage
#pragma unroll
        for (int i = 0; i < 2; i++) {
            float2 v;
            v.x = pm * acc[i * 2 + 0][ch] * inv[i * 2 + 0];
            v.y = pm * acc[i * 2 + 1][ch] * inv[i * 2 + 1];
            *reinterpret_cast<float2*>(ob + (size_t)ch * HW4 + (size_t)i * W2) = v;
        }
    }
}

template<int H, int WSHIFT, bool FIRST, int TPB, int MINB, int MODE, bool TRIG>
static inline void launch_stage(const float* pf, const float* pd,
                                const float* mask, float* out, int N)
{
    constexpr int HW = H << WSHIFT;
    static_assert(HW % TPB == 0, "exact grid");

    cudaLaunchConfig_t cfg = {};
    cfg.gridDim  = dim3(HW / TPB, N);
    cfg.blockDim = dim3(TPB);
    cudaLaunchAttribute attr[1];
    attr[0].id = cudaLaunchAttributeProgrammaticStreamSerialization;
    attr[0].val.programmaticStreamSerializationAllowed = 1;
    if (MODE != 0) { cfg.attrs = attr; cfg.numAttrs = 1; }

    cudaLaunchKernelEx(&cfg,
                       convex_up<H, WSHIFT, FIRST, TPB, MINB, MODE, TRIG>,
                       pf, pd, mask, out);
}

extern "C" void kernel_launch(void* const* d_in, const int* in_sizes, int n_in,
                              void* d_out, int out_size)
{
    const float* flow16 = (const float*)d_in[0];  // [4,2,48,64]
    const float* dz16   = (const float*)d_in[1];  // [4,1,48,64]
    const float* mask16 = (const float*)d_in[2];  // [4,36,48,64]
    const float* mask8  = (const float*)d_in[3];  // [4,36,96,128]
    const float* mask4  = (const float*)d_in[4];  // [4,36,192,256]
    const float* mask2  = (const float*)d_in[5];  // [4,36,384,512]
    float* out = (float*)d_out;                   // [4,3,768,1024]

    float *buf1, *buf2, *buf3;
    cudaGetSymbolAddress((void**)&buf1, g_buf1);
    cudaGetSymbolAddress((void**)&buf2, g_buf2);
    cudaGetSymbolAddress((void**)&buf3, g_buf3);

    const int N = 4;

    // Stage 1: no wait, trigger.
    launch_stage<48, 6, true, 64, 8, 0, true>(flow16, dz16, mask16, buf1, N);
    // Stage 2: phase-1 denominators (mask8 L2-resident), trigger.
    launch_stage<96, 7, false, 64, 8, 1, true>(buf1, buf1 + 2 * 96 * 128,
                                               mask8, buf2, N);
    // Stage 3: phase-1 denominators (mask4 L2-resident), trigger.
    launch_stage<192, 8, false, 256, 5, 1, true>(buf2, buf2 + 2 * 192 * 256,
                                                 mask4, buf3, N);
    // Stage 4: plain wait + proven single pass (R13 config), no trigger.
    launch_stage<384, 9, false, 256, 5, 3, false>(buf3, buf3 + 2 * 384 * 512,
                                                  mask2, out, N);
}

// round 16
// speedup vs baseline: 1.0997x; 1.0077x over previous
#include <cuda_runtime.h>

// Ping-pong scratch (device globals — no allocation allowed).
__device__ float g_buf1[4 * 3 * 96  * 128];   // stage1 out
__device__ float g_buf2[4 * 3 * 192 * 256];   // stage2 out
__device__ float g_buf3[4 * 3 * 384 * 512];   // stage3 out

__device__ __forceinline__ void pdl_trigger() {
    asm volatile("griddepcontrol.launch_dependents;" ::: "memory");
}
__device__ __forceinline__ void pdl_wait() {
    asm volatile("griddepcontrol.wait;" ::: "memory");
}

// One convex-upsample stage (scale=2). Thread = one SOURCE pixel (n,h,w),
// producing the 2x2 output quad for all 3 channels.
// mask layout [N,36,H,W], channel c = k*4 + i*2 + j.
// Softmax over k without max-subtraction (exp of ~N(0,1) safe; identical).
//
// MODE 0: first stage — single pass, no wait.
// MODE 1: phase-1 softmax denominators pre-wait; phase-2 re-reads mask from
//         L2 (mask must be L2-resident).                     [R14: works]
// MODE 3: plain wait then single pass.                       [R15 stage 4]
// MODE 4: phase-1 pre-wait streams mask, computes exp, STORES exp values in
//         per-thread smem slots (smk[c][tid], no barriers needed) + sums.
//         Phase-2 is pure LDS+FMA — no second mask read, no second exp.
//         Moves each resident CTA's entire mask DRAM stream ahead of the
//         producer dependency (fixes R10's DRAM re-read failure).
template<int H, int WSHIFT, bool FIRST, int TPB, int MINB, int MODE, bool TRIG>
__global__ __launch_bounds__(TPB, MINB)
void convex_up(const float* __restrict__ in_flow,
               const float* __restrict__ in_dz,
               const float* __restrict__ mask,
               float* __restrict__ out)
{
    constexpr int W  = 1 << WSHIFT;
    constexpr int HW = H * W;

    __shared__ float smk[(MODE == 4) ? 36 : 1][(MODE == 4) ? TPB : 1];

    if (TRIG) pdl_trigger();   // release dependent stage's CTAs immediately

    const int tid = threadIdx.x;
    const int idx = blockIdx.x * TPB + tid;           // grid exact: no guard
    const int n = blockIdx.y;
    const int w = idx & (W - 1);
    const int h = idx >> WSHIFT;

    const float* mb = mask + (size_t)n * (36 * HW) + idx;   // + c*HW per channel
    const float* pf = in_flow + (size_t)n * (FIRST ? 2 * HW : 3 * HW);
    const float* pd = in_dz   + (size_t)n * (FIRST ?     HW : 3 * HW);

    // Hoisted edge predicates (producer-independent).
    const bool okl = (w > 0), okr = (w + 1 < W);
    const bool oku = (h > 0), okd = (h + 1 < H);

    float sum[4] = {0.f, 0.f, 0.f, 0.f};
    float inv[4];

    if (MODE == 1) {
#pragma unroll
        for (int k = 0; k < 9; k++)
#pragma unroll
            for (int q = 0; q < 4; q++)
                sum[q] += __expf(__ldcg(mb + (size_t)(k * 4 + q) * HW));
#pragma unroll
        for (int q = 0; q < 4; q++) inv[q] = __fdividef(1.0f, sum[q]);
        pdl_wait();
    } else if (MODE == 4) {
        // ---- phase 1: mask stream -> exp -> smem + denominators, pre-wait ----
#pragma unroll
        for (int k = 0; k < 9; k++) {
#pragma unroll
            for (int q = 0; q < 4; q++) {
                const int c = k * 4 + q;
                float e = __expf(__ldcs(mb + (size_t)c * HW));
                smk[c][tid] = e;
                sum[q] += e;
            }
        }
#pragma unroll
        for (int q = 0; q < 4; q++) inv[q] = __fdividef(1.0f, sum[q]);
        pdl_wait();
    } else if (MODE == 3) {
        pdl_wait();
    }

    float acc[4][3];
#pragma unroll
    for (int q = 0; q < 4; q++) acc[q][0] = acc[q][1] = acc[q][2] = 0.f;

#pragma unroll
    for (int k = 0; k < 9; k++) {
        const int dy = k / 3 - 1;
        const int dx = k % 3 - 1;
        const bool ok = (dy == 0 || (dy < 0 ? oku : okd)) &&
                        (dx == 0 || (dx < 0 ? okl : okr));
        float v0 = 0.f, v1 = 0.f, v2 = 0.f;
        if (ok) {
            const int off = ((h + dy) << WSHIFT) + (w + dx);
            v0 = pf[off];
            v1 = pf[off + HW];
            v2 = pd[off];
        }
#pragma unroll
        for (int q = 0; q < 4; q++) {
            float e;
            if (MODE == 1)
                e = __expf(__ldcg(mb + (size_t)(k * 4 + q) * HW));  // L2 hit
            else if (MODE == 4)
                e = smk[k * 4 + q][tid];                            // LDS only
            else
                e = __expf(__ldcs(mb + (size_t)(k * 4 + q) * HW));
            if (MODE != 1 && MODE != 4) sum[q] += e;
            acc[q][0] = fmaf(e, v0, acc[q][0]);
            acc[q][1] = fmaf(e, v1, acc[q][1]);
            acc[q][2] = fmaf(e, v2, acc[q][2]);
        }
    }

    if (MODE != 1 && MODE != 4) {
#pragma unroll
        for (int q = 0; q < 4; q++) inv[q] = __fdividef(1.0f, sum[q]);
    }

    // out [N,3,2H,2W]; quad q = i*2+j -> pixel (2h+i, 2w+j). float2 stores.
    constexpr int W2 = W << 1;
    constexpr size_t HW4 = (size_t)HW * 4;
    float* ob = out + (size_t)n * (3 * HW4)
                    + ((size_t)h << (WSHIFT + 2)) + (w << 1);
#pragma unroll
    for (int ch = 0; ch < 3; ch++) {
        const float pm = (ch < 2) ? 2.0f : 1.0f;   // flow premul per stage
#pragma unroll
        for (int i = 0; i < 2; i++) {
            float2 v;
            v.x = pm * acc[i * 2 + 0][ch] * inv[i * 2 + 0];
            v.y = pm * acc[i * 2 + 1][ch] * inv[i * 2 + 1];
            *reinterpret_cast<float2*>(ob + (size_t)ch * HW4 + (size_t)i * W2) = v;
        }
    }
}

template<int H, int WSHIFT, bool FIRST, int TPB, int MINB, int MODE, bool TRIG>
static inline void launch_stage(const float* pf, const float* pd,
                                const float* mask, float* out, int N)
{
    constexpr int HW = H << WSHIFT;
    static_assert(HW % TPB == 0, "exact grid");

    cudaLaunchConfig_t cfg = {};
    cfg.gridDim  = dim3(HW / TPB, N);
    cfg.blockDim = dim3(TPB);
    cudaLaunchAttribute attr[1];
    attr[0].id = cudaLaunchAttributeProgrammaticStreamSerialization;
    attr[0].val.programmaticStreamSerializationAllowed = 1;
    if (MODE != 0) { cfg.attrs = attr; cfg.numAttrs = 1; }

    cudaLaunchKernelEx(&cfg,
                       convex_up<H, WSHIFT, FIRST, TPB, MINB, MODE, TRIG>,
                       pf, pd, mask, out);
}

extern "C" void kernel_launch(void* const* d_in, const int* in_sizes, int n_in,
                              void* d_out, int out_size)
{
    const float* flow16 = (const float*)d_in[0];  // [4,2,48,64]
    const float* dz16   = (const float*)d_in[1];  // [4,1,48,64]
    const float* mask16 = (const float*)d_in[2];  // [4,36,48,64]
    const float* mask8  = (const float*)d_in[3];  // [4,36,96,128]
    const float* mask4  = (const float*)d_in[4];  // [4,36,192,256]
    const float* mask2  = (const float*)d_in[5];  // [4,36,384,512]
    float* out = (float*)d_out;                   // [4,3,768,1024]

    float *buf1, *buf2, *buf3;
    cudaGetSymbolAddress((void**)&buf1, g_buf1);
    cudaGetSymbolAddress((void**)&buf2, g_buf2);
    cudaGetSymbolAddress((void**)&buf3, g_buf3);

    const int N = 4;

    // Stage 1: no wait, trigger.
    launch_stage<48, 6, true, 64, 8, 0, true>(flow16, dz16, mask16, buf1, N);
    // Stage 2: MODE 1 (mask8 L2-resident re-read), trigger.       [proven]
    launch_stage<96, 7, false, 64, 8, 1, true>(buf1, buf1 + 2 * 96 * 128,
                                               mask8, buf2, N);
    // Stage 3: MODE 4 smem-staged phase-1 (whole grid ~1 wave), trigger.
    launch_stage<192, 8, false, 256, 5, 4, true>(buf2, buf2 + 2 * 192 * 256,
                                                 mask4, buf3, N);
    // Stage 4: MODE 4 smem-staged phase-1 (first wave overlaps stage 3).
    launch_stage<384, 9, false, 256, 5, 4, false>(buf3, buf3 + 2 * 384 * 512,
                                                  mask2, out, N);
}